// round 5
// baseline (speedup 1.0000x reference)
#include <cuda_runtime.h>
#include <math.h>
#include <stdint.h>
#include <stddef.h>

// Problem constants (shapes fixed by the dataset)
#define NN   10000
#define EE   160000
#define HD   32      // hidden
#define NDD  64      // node_dim
#define EDD  16      // edge_dim
#define MHH  128     // edge mlp hidden

#define GNODES 8                     // src nodes per fused block
#define PSTRIDE 132                  // smem row stride (floats) for P rows

// ---------------- scratch (device globals; no allocation allowed) ----------
__device__ int   g_is64;
__device__ int   g_src[EE], g_dst[EE];
__device__ int   g_cnt_src[NN], g_cnt_dst[NN];
__device__ int   g_off_src[NN + 1], g_off_dst[NN + 1];
__device__ int   g_cur_src[NN], g_cur_dst[NN];
__device__ int   g_ebysrc[EE], g_ebydst[EE];
__device__ float g_h[NN * HD];
__device__ float g_z[(size_t)EE * MHH];          // relu(ea@W1+b1)      82 MB
__device__ float g_W2t[HD * MHH * HD];           // [j][i*128+m] = W2[m][i*32+j]
__device__ float g_b2t[HD * HD];                 // [j][i] = b2[i*32+j]
__device__ float g_msg[(size_t)EE * HD];         // per-edge message    20 MB

// ---------------- setup kernels -------------------------------------------

// Detect int64 vs int32 edge_index: int64 little-endian => every odd 32-bit
// word of the first 128 (src) entries is 0 (values in [0,10000)).
__global__ void k_detect(const int* __restrict__ w) {
    __shared__ int ok;
    if (threadIdx.x == 0) ok = 1;
    __syncthreads();
    if (w[2 * threadIdx.x + 1] != 0) atomicExch(&ok, 0);
    __syncthreads();
    if (threadIdx.x == 0) g_is64 = ok;
}

__global__ void k_zero_counts(int nN) {
    int i = blockIdx.x * 256 + threadIdx.x;
    if (i < nN) { g_cnt_src[i] = 0; g_cnt_dst[i] = 0; }
}

// Extract src/dst as int32 (branch on detected dtype) + degree histograms.
__global__ void k_extract(const int* __restrict__ w, int nE) {
    int e = blockIdx.x * 256 + threadIdx.x;
    if (e >= nE) return;
    int is64 = g_is64;
    int s, d;
    if (is64) { s = w[2 * e]; d = w[2 * (nE + e)]; }
    else      { s = w[e];     d = w[nE + e]; }
    g_src[e] = s; g_dst[e] = d;
    atomicAdd(&g_cnt_src[s], 1);
    atomicAdd(&g_cnt_dst[d], 1);
}

// Fast exclusive scan: per-thread sequential + warp/block shuffle scan.
// blockIdx 0 -> src arrays, 1 -> dst arrays.
__global__ __launch_bounds__(1024) void k_scan(int nN) {
    int* cnt = blockIdx.x ? g_cnt_dst : g_cnt_src;
    int* off = blockIdx.x ? g_off_dst : g_off_src;
    int* cur = blockIdx.x ? g_cur_dst : g_cur_src;
    const int CH = 10;                 // 1024*10 >= 10000
    int tid = threadIdx.x, lane = tid & 31, w = tid >> 5;
    int base = tid * CH;
    int v[CH];
    int s = 0;
#pragma unroll
    for (int q = 0; q < CH; q++) {
        int i = base + q;
        v[q] = (i < nN) ? cnt[i] : 0;
        s += v[q];
    }
    int sc = s;
#pragma unroll
    for (int o = 1; o < 32; o <<= 1) {
        int t = __shfl_up_sync(0xffffffffu, sc, o);
        if (lane >= o) sc += t;
    }
    __shared__ int wt[32];
    if (lane == 31) wt[w] = sc;
    __syncthreads();
    if (w == 0) {
        int t = wt[lane];
#pragma unroll
        for (int o = 1; o < 32; o <<= 1) {
            int u = __shfl_up_sync(0xffffffffu, t, o);
            if (lane >= o) t += u;
        }
        wt[lane] = t;
    }
    __syncthreads();
    int excl = sc - s + (w ? wt[w - 1] : 0);
    int run = excl;
#pragma unroll
    for (int q = 0; q < CH; q++) {
        int i = base + q;
        if (i < nN) { off[i] = run; cur[i] = run; run += v[q]; }
    }
    if (tid == 1023) off[nN] = excl + s;
}

__global__ void k_fill(int nE) {
    int e = blockIdx.x * 256 + threadIdx.x;
    if (e >= nE) return;
    int s = g_src[e], d = g_dst[e];
    int p = atomicAdd(&g_cur_src[s], 1); g_ebysrc[p] = e;
    int q = atomicAdd(&g_cur_dst[d], 1); g_ebydst[q] = e;
}

// W2t[j*4096 + i*128 + m] = W2[m*1024 + i*32 + j]  (msg-friendly permutation)
// b2t[j*32+i] = b2[i*32+j]
__global__ void k_w2t(const float* __restrict__ W2, const float* __restrict__ b2) {
    int t = blockIdx.x * 256 + threadIdx.x;
    if (t < HD * MHH * HD) {
        int j = t >> 12, i = (t >> 7) & 31, m = t & 127;
        g_W2t[t] = W2[m * 1024 + i * 32 + j];
    }
    int t2 = t - HD * MHH * HD;
    if (t2 >= 0 && t2 < HD * HD) {
        int j = t2 >> 5, i = t2 & 31;
        g_b2t[t2] = b2[i * 32 + j];
    }
}

// h0 = x @ Wp + bp   (warp per node)
__global__ __launch_bounds__(256) void k_h0(const float* __restrict__ x,
                                            const float* __restrict__ Wp,
                                            const float* __restrict__ bp, int nN) {
    __shared__ float Ws[NDD * HD];
    __shared__ float bs[HD];
    int tid = threadIdx.x;
    for (int i = tid; i < NDD * HD; i += 256) Ws[i] = Wp[i];
    if (tid < HD) bs[tid] = bp[tid];
    __syncthreads();
    int w = tid >> 5, lane = tid & 31;
    int n = blockIdx.x * 8 + w;
    if (n >= nN) return;
    float x0 = x[n * 64 + lane], x1 = x[n * 64 + 32 + lane];
    float acc = bs[lane];
#pragma unroll
    for (int j = 0; j < 32; j++) acc += __shfl_sync(0xffffffffu, x0, j) * Ws[j * 32 + lane];
#pragma unroll
    for (int j = 0; j < 32; j++) acc += __shfl_sync(0xffffffffu, x1, j) * Ws[(32 + j) * 32 + lane];
    g_h[n * 32 + lane] = acc;
}

// z = relu(ea @ W1 + b1)   (warp per edge)
__global__ __launch_bounds__(256) void k_z(const float* __restrict__ ea,
                                           const float* __restrict__ W1,
                                           const float* __restrict__ b1, int nE) {
    __shared__ float Ws[EDD * MHH];
    __shared__ float bs[MHH];
    int tid = threadIdx.x;
    for (int i = tid; i < EDD * MHH; i += 256) Ws[i] = W1[i];
    if (tid < MHH) bs[tid] = b1[tid];
    __syncthreads();
    int w = tid >> 5, lane = tid & 31;
    int e = blockIdx.x * 8 + w;
    if (e >= nE) return;
    float a0 = (lane < 16) ? ea[e * 16 + lane] : 0.f;
    float acc0 = bs[lane], acc1 = bs[32 + lane], acc2 = bs[64 + lane], acc3 = bs[96 + lane];
#pragma unroll
    for (int j = 0; j < 16; j++) {
        float a = __shfl_sync(0xffffffffu, a0, j);
        acc0 += a * Ws[j * 128 + lane];
        acc1 += a * Ws[j * 128 + 32 + lane];
        acc2 += a * Ws[j * 128 + 64 + lane];
        acc3 += a * Ws[j * 128 + 96 + lane];
    }
    float* zp = &g_z[(size_t)e * 128];
    zp[lane]      = fmaxf(acc0, 0.f);
    zp[32 + lane] = fmaxf(acc1, 0.f);
    zp[64 + lane] = fmaxf(acc2, 0.f);
    zp[96 + lane] = fmaxf(acc3, 0.f);
}

// ---------------- per-step fused kernel -----------------------------------
//
// Block owns GNODES=8 consecutive src nodes. Phase 1 computes their P rows
// (P[n,i,m] = sum_j h[n,j] * W2t[j, i*128+m]) into shared memory — W2t is
// 512 KB and stays L2-resident across all 1250 blocks. Phase 2 applies all
// out-edges of those nodes (contiguous in src-CSR):
//   msg[e,i] = C[src_e,i] + sum_m z[e,m] * P[src_e,i,m]
// P never touches HBM.
//
// Dynamic smem layout (floats):
//   Ps [8][32][PSTRIDE=132]   33792
//   zb [8 warps][4 edges][128] 4096
//   hs [8][33]                  264
//   Cn [8][32]                  256
#define SMEM_FLOATS (GNODES * HD * PSTRIDE + 8 * 4 * MHH + GNODES * 33 + GNODES * HD)

__global__ __launch_bounds__(256) void k_pmsg(int nN) {
    extern __shared__ float sm[];
    float* Ps = sm;
    float* zb = sm + GNODES * HD * PSTRIDE;
    float* hs = zb + 8 * 4 * MHH;
    float* Cn = hs + GNODES * 33;

    int tid = threadIdx.x, warp = tid >> 5, lane = tid & 31;
    int n0 = blockIdx.x * GNODES;

    // load h for the 8 nodes (thread (n,j))
    {
        int n = tid >> 5, j = tid & 31;
        int gn = n0 + n;
        hs[n * 33 + j] = (gn < nN) ? g_h[gn * 32 + j] : 0.f;
    }
    __syncthreads();

    // C[n,i] = sum_j h[n,j] * b2t[j,i]   (thread (n,i))
    {
        int n = tid >> 5, i = tid & 31;
        float acc = 0.f;
#pragma unroll
        for (int j = 0; j < 32; j++) acc += hs[n * 33 + j] * g_b2t[j * 32 + i];
        Cn[n * 32 + i] = acc;
    }

    // Phase 1: P into smem. 1024 float4-groups; thread handles 4 of them.
#pragma unroll
    for (int q = 0; q < 4; q++) {
        int rem = (tid + q * 256) * 4;          // 0..4092, step 4
        int i = rem >> 7, m = rem & 127;
        float4 acc[GNODES];
#pragma unroll
        for (int n = 0; n < GNODES; n++) acc[n] = make_float4(0.f, 0.f, 0.f, 0.f);
#pragma unroll 8
        for (int j = 0; j < 32; j++) {
            float4 wv = *(const float4*)&g_W2t[j * 4096 + rem];
#pragma unroll
            for (int n = 0; n < GNODES; n++) {
                float hv = hs[n * 33 + j];
                acc[n].x += hv * wv.x; acc[n].y += hv * wv.y;
                acc[n].z += hv * wv.z; acc[n].w += hv * wv.w;
            }
        }
#pragma unroll
        for (int n = 0; n < GNODES; n++)
            *(float4*)&Ps[(n * 32 + i) * PSTRIDE + m] = acc[n];
    }
    __syncthreads();

    // Phase 2: edges of nodes n0..n0+7 (contiguous in src-CSR).
    int nhi = n0 + GNODES; if (nhi > nN) nhi = nN;
    int eb = g_off_src[n0];
    int ee = g_off_src[nhi];
    for (int base = eb + warp * 4; base < ee; base += 32) {
        int cnt = ee - base; if (cnt > 4) cnt = 4;
        int eidx[4], nl[4];
#pragma unroll
        for (int k = 0; k < 4; k++) {
            if (k < cnt) {
                int e = g_ebysrc[base + k];
                eidx[k] = e;
                nl[k] = g_src[e] - n0;
                *(float4*)&zb[(warp * 4 + k) * 128 + lane * 4] =
                    *(const float4*)&g_z[(size_t)e * 128 + lane * 4];
            } else nl[k] = 0;
        }
        __syncwarp();
        float acc[4];
#pragma unroll
        for (int k = 0; k < 4; k++) acc[k] = Cn[nl[k] * 32 + lane];
#pragma unroll 8
        for (int m4 = 0; m4 < 32; m4++) {
#pragma unroll
            for (int k = 0; k < 4; k++) {
                float4 p  = *(const float4*)&Ps[(nl[k] * 32 + lane) * PSTRIDE + m4 * 4];
                float4 zv = *(const float4*)&zb[(warp * 4 + k) * 128 + m4 * 4];
                acc[k] += p.x * zv.x + p.y * zv.y + p.z * zv.z + p.w * zv.w;
            }
        }
#pragma unroll
        for (int k = 0; k < 4; k++)
            if (k < cnt) g_msg[(size_t)eidx[k] * 32 + lane] = acc[k];
        __syncwarp();
    }
}

// Fused aggregation (dst-CSR gather) + GRUCell (torch layout [r,z,n]).
__global__ __launch_bounds__(256) void k_agg_gru(const float* __restrict__ wih,
                                                 const float* __restrict__ whh,
                                                 const float* __restrict__ bih,
                                                 const float* __restrict__ bhh,
                                                 float* __restrict__ out, int nN) {
    __shared__ float wi[32 * 96];   // wi[j*96+k] = wih[k*32+j]
    __shared__ float wh[32 * 96];
    __shared__ float bi[96], bh[96];
    int tid = threadIdx.x;
    for (int idx = tid; idx < 3072; idx += 256) {
        int k = idx >> 5, j = idx & 31;
        wi[j * 96 + k] = wih[idx];
        wh[j * 96 + k] = whh[idx];
    }
    if (tid < 96) { bi[tid] = bih[tid]; bh[tid] = bhh[tid]; }
    __syncthreads();
    int w = tid >> 5, lane = tid & 31;
    int n = blockIdx.x * 8 + w;
    if (n >= nN) return;

    int o = g_off_dst[n], d = g_off_dst[n + 1] - o;
    float av = 0.f;
    for (int k = 0; k < d; k++) {
        int e = g_ebydst[o + k];
        av += g_msg[(size_t)e * 32 + lane];
    }
    float hv = g_h[n * 32 + lane];

    float gi0 = bi[lane], gi1 = bi[32 + lane], gi2 = bi[64 + lane];
    float gh0 = bh[lane], gh1 = bh[32 + lane], gh2 = bh[64 + lane];
#pragma unroll
    for (int j = 0; j < 32; j++) {
        float a = __shfl_sync(0xffffffffu, av, j);
        float h = __shfl_sync(0xffffffffu, hv, j);
        gi0 += a * wi[j * 96 + lane];
        gi1 += a * wi[j * 96 + 32 + lane];
        gi2 += a * wi[j * 96 + 64 + lane];
        gh0 += h * wh[j * 96 + lane];
        gh1 += h * wh[j * 96 + 32 + lane];
        gh2 += h * wh[j * 96 + 64 + lane];
    }
    float r  = 1.f / (1.f + expf(-(gi0 + gh0)));
    float zz = 1.f / (1.f + expf(-(gi1 + gh1)));
    float nn = tanhf(gi2 + r * gh2);
    float hn = (1.f - zz) * nn + zz * hv;
    g_h[n * 32 + lane] = hn;
    out[n * 32 + lane] = hn;
}

// ---------------- launch ---------------------------------------------------

extern "C" void kernel_launch(void* const* d_in, const int* in_sizes, int n_in,
                              void* d_out, int out_size) {
    const float* x   = (const float*)d_in[0];
    const int*   ei  = (const int*)d_in[1];
    const float* ea  = (const float*)d_in[2];
    const float* Wp  = (const float*)d_in[3];
    const float* bp  = (const float*)d_in[4];
    const float* W1  = (const float*)d_in[5];
    const float* b1  = (const float*)d_in[6];
    const float* W2  = (const float*)d_in[7];
    const float* b2  = (const float*)d_in[8];
    const float* wih = (const float*)d_in[9];
    const float* whh = (const float*)d_in[10];
    const float* bih = (const float*)d_in[11];
    const float* bhh = (const float*)d_in[12];
    float* out = (float*)d_out;

    int nN = in_sizes[0] / NDD; if (nN > NN) nN = NN;
    int nE = in_sizes[2] / EDD; if (nE > EE) nE = EE;

    const int smem_bytes = SMEM_FLOATS * 4;   // ~153.6 KB
    cudaFuncSetAttribute(k_pmsg, cudaFuncAttributeMaxDynamicSharedMemorySize, smem_bytes);

    // ---- setup (per launch, deterministic) ----
    k_zero_counts<<<(nN + 255) / 256, 256>>>(nN);
    k_detect<<<1, 128>>>(ei);
    k_extract<<<(nE + 255) / 256, 256>>>(ei, nE);
    k_scan<<<2, 1024>>>(nN);
    k_fill<<<(nE + 255) / 256, 256>>>(nE);
    k_w2t<<<(HD * MHH * HD + HD * HD + 255) / 256, 256>>>(W2, b2);
    k_h0<<<(nN + 7) / 8, 256>>>(x, Wp, bp, nN);
    k_z<<<(nE + 7) / 8, 256>>>(ea, W1, b1, nE);

    // ---- 3 message-passing steps ----
    int gF = (nN + GNODES - 1) / GNODES;
    for (int step = 0; step < 3; step++) {
        k_pmsg<<<gF, 256, smem_bytes>>>(nN);
        k_agg_gru<<<(nN + 7) / 8, 256>>>(wih, whh, bih, bhh, out, nN);
    }
}